// round 5
// baseline (speedup 1.0000x reference)
#include <cuda_runtime.h>
#include <cuda_bf16.h>
#include <cstdint>
#include <math.h>

#define NB    8
#define CIN   512
#define KCC   256
#define KK    19
#define HW    16384
#define TOT   (NB * HW)
#define EPSF  1e-5f

// ---------------------------------------------------------------------------
// Scratch (device globals; no cudaMalloc)
// ---------------------------------------------------------------------------
__device__ __nv_bfloat16 g_xh[(size_t)CIN * TOT];    // x hi plane  [nb][C][HW]
__device__ __nv_bfloat16 g_xl[(size_t)CIN * TOT];    // x lo plane
__device__ __nv_bfloat16 g_t1h[(size_t)KCC * TOT];   // t1 hi [256][TOT]
__device__ __nv_bfloat16 g_t1l[(size_t)KCC * TOT];
__device__ float         g_q[(size_t)KCC * TOT];     // q fp32 [256][TOT]
__device__ __nv_bfloat16 g_ch[(size_t)KCC * TOT];    // ctx hi [256][TOT]
__device__ __nv_bfloat16 g_cl[(size_t)KCC * TOT];
__device__ __nv_bfloat16 g_w1h[KCC * CIN], g_w1l[KCC * CIN];
__device__ __nv_bfloat16 g_w2h[KCC * KCC], g_w2l[KCC * KCC];
__device__ __nv_bfloat16 g_wuh[CIN * KCC], g_wul[CIN * KCC];
__device__ float g_kbuf[NB * KCC * KK];
__device__ float g_vbuf[NB * KCC * KK];

static __device__ __forceinline__ uint32_t smem_u32(const void* p) {
    uint32_t a;
    asm("{ .reg .u64 t; cvta.to.shared.u64 t, %1; cvt.u32.u64 %0, t; }"
        : "=r"(a) : "l"(p));
    return a;
}

#define LDSM4(r0, r1, r2, r3, addr) \
    asm volatile("ldmatrix.sync.aligned.m8n8.x4.shared.b16 {%0,%1,%2,%3}, [%4];" \
                 : "=r"(r0), "=r"(r1), "=r"(r2), "=r"(r3) : "r"(addr))

#define LDSM4T(r0, r1, r2, r3, addr) \
    asm volatile("ldmatrix.sync.aligned.m8n8.x4.trans.shared.b16 {%0,%1,%2,%3}, [%4];" \
                 : "=r"(r0), "=r"(r1), "=r"(r2), "=r"(r3) : "r"(addr))

#define MMA(d, a, b) \
    asm volatile("mma.sync.aligned.m16n8k16.row.col.f32.bf16.bf16.f32 " \
                 "{%0,%1,%2,%3}, {%4,%5,%6,%7}, {%8,%9}, {%0,%1,%2,%3};" \
                 : "+f"((d)[0]), "+f"((d)[1]), "+f"((d)[2]), "+f"((d)[3]) \
                 : "r"((a)[0]), "r"((a)[1]), "r"((a)[2]), "r"((a)[3]), \
                   "r"((b)[0]), "r"((b)[1]))

// ---------------------------------------------------------------------------
// fp32 -> hi/lo bf16 planes (vectorized by 4)
// ---------------------------------------------------------------------------
__global__ void __launch_bounds__(256) split_kernel(
    const float* __restrict__ s, __nv_bfloat16* __restrict__ h,
    __nv_bfloat16* __restrict__ l, size_t n4)
{
    size_t idx = (size_t)blockIdx.x * 256 + threadIdx.x;
    if (idx >= n4) return;
    float4 v = ((const float4*)s)[idx];
    __nv_bfloat162 h01 = __float22bfloat162_rn(make_float2(v.x, v.y));
    __nv_bfloat162 h23 = __float22bfloat162_rn(make_float2(v.z, v.w));
    float2 f01 = __bfloat1622float2(h01);
    float2 f23 = __bfloat1622float2(h23);
    __nv_bfloat162 l01 = __float22bfloat162_rn(make_float2(v.x - f01.x, v.y - f01.y));
    __nv_bfloat162 l23 = __float22bfloat162_rn(make_float2(v.z - f23.x, v.w - f23.y));
    ((__nv_bfloat162*)h)[2 * idx]     = h01;
    ((__nv_bfloat162*)h)[2 * idx + 1] = h23;
    ((__nv_bfloat162*)l)[2 * idx]     = l01;
    ((__nv_bfloat162*)l)[2 * idx + 1] = l23;
}

// ---------------------------------------------------------------------------
// Proxy path (tiny): k,v  [n][ch][19]
// ---------------------------------------------------------------------------
__global__ void __launch_bounds__(KCC) proxy_kernel(
    const float* __restrict__ proxy,
    const float* __restrict__ w_o1, const float* __restrict__ o1g,
    const float* __restrict__ o1b,  const float* __restrict__ o1m,
    const float* __restrict__ o1v,
    const float* __restrict__ w_o2, const float* __restrict__ o2g,
    const float* __restrict__ o2b,  const float* __restrict__ o2m,
    const float* __restrict__ o2v,
    const float* __restrict__ w_d,  const float* __restrict__ dgv,
    const float* __restrict__ dbv,  const float* __restrict__ dmv,
    const float* __restrict__ dvv)
{
    const int n  = blockIdx.x;
    const int ch = threadIdx.x;
    const float* p = proxy + n * CIN * KK;

    __shared__ float t_sh[KCC * KK];

    float acc1[KK], accv[KK];
#pragma unroll
    for (int j = 0; j < KK; j++) { acc1[j] = 0.f; accv[j] = 0.f; }

    for (int c = 0; c < CIN; c++) {
        float w1 = __ldg(&w_o1[ch * CIN + c]);
        float wd = __ldg(&w_d [ch * CIN + c]);
#pragma unroll
        for (int j = 0; j < KK; j++) {
            float pv = __ldg(&p[c * KK + j]);
            acc1[j] = fmaf(w1, pv, acc1[j]);
            accv[j] = fmaf(wd, pv, accv[j]);
        }
    }
    {
        float inv = o1g[ch] * rsqrtf(o1v[ch] + EPSF);
        float bt  = o1b[ch] - o1m[ch] * inv;
#pragma unroll
        for (int j = 0; j < KK; j++)
            t_sh[ch * KK + j] = fmaxf(fmaf(acc1[j], inv, bt), 0.f);
    }
    {
        float inv = dgv[ch] * rsqrtf(dvv[ch] + EPSF);
        float bt  = dbv[ch] - dmv[ch] * inv;
#pragma unroll
        for (int j = 0; j < KK; j++)
            g_vbuf[(n * KCC + ch) * KK + j] = fmaxf(fmaf(accv[j], inv, bt), 0.f);
    }
    __syncthreads();

    float acc2[KK];
#pragma unroll
    for (int j = 0; j < KK; j++) acc2[j] = 0.f;
    for (int c = 0; c < KCC; c++) {
        float w2 = __ldg(&w_o2[ch * KCC + c]);
#pragma unroll
        for (int j = 0; j < KK; j++)
            acc2[j] = fmaf(w2, t_sh[c * KK + j], acc2[j]);
    }
    {
        float inv = o2g[ch] * rsqrtf(o2v[ch] + EPSF);
        float bt  = o2b[ch] - o2m[ch] * inv;
#pragma unroll
        for (int j = 0; j < KK; j++)
            g_kbuf[(n * KCC + ch) * KK + j] = fmaxf(fmaf(acc2[j], inv, bt), 0.f);
    }
}

// ---------------------------------------------------------------------------
// HMMA GEMM (pre-split operands): D = bn_relu( A(hi/lo) @ B(hi/lo) ), 3 terms.
// BM=256 BN=128 BK=32, 256 threads, warp tile 64x64.
// MODE 0: write hi/lo bf16 planes; MODE 1: write fp32.
// ---------------------------------------------------------------------------
#define OFF_AH 0
#define OFF_AL 16384
#define OFF_BH 32768
#define OFF_BL 40960

template <int MODE>
__global__ void __launch_bounds__(256, 1) gemm_mma(
    const __nv_bfloat16* __restrict__ Ah, const __nv_bfloat16* __restrict__ Al, int KT,
    const __nv_bfloat16* __restrict__ Bh, const __nv_bfloat16* __restrict__ Bl,
    int bRow, long bBatch,
    float* __restrict__ Cf, __nv_bfloat16* __restrict__ Ch, __nv_bfloat16* __restrict__ Cl,
    int cRow, long cBatch,
    const float* __restrict__ gg, const float* __restrict__ bb,
    const float* __restrict__ mm, const float* __restrict__ vv)
{
    __shared__ __align__(128) unsigned char sm[49152];
    const uint32_t sb = smem_u32(sm);

    const int tid  = threadIdx.x;
    const int lane = tid & 31;
    const int w    = tid >> 5;
    const int mw   = (w >> 1) * 64;
    const int nw   = (w & 1) * 64;

    const int nBase = blockIdx.x * 128;
    const int mBase = blockIdx.y * 256;
    const int nbat  = nBase >> 14;
    const int hw0   = nBase & (HW - 1);

    const __nv_bfloat16* Bph = Bh + (size_t)nbat * bBatch + hw0;
    const __nv_bfloat16* Bpl = Bl + (size_t)nbat * bBatch + hw0;

    // staging: A row per thread (4 quads each plane); B: k = tid>>3, 2 quads each plane
    const int bk    = tid >> 3;
    const int bu0   = (tid & 7) * 2;

    float acc[4][8][4];
#pragma unroll
    for (int i = 0; i < 4; i++)
#pragma unroll
        for (int g = 0; g < 8; g++)
#pragma unroll
            for (int r = 0; r < 4; r++) acc[i][g][r] = 0.f;

    uint4 pah[4], pal[4], pbh[2], pbl[2];
    {
        const __nv_bfloat16* ar = Ah + (size_t)(mBase + tid) * KT;
        const __nv_bfloat16* al = Al + (size_t)(mBase + tid) * KT;
#pragma unroll
        for (int q = 0; q < 4; q++) {
            pah[q] = *(const uint4*)(ar + 8 * q);
            pal[q] = *(const uint4*)(al + 8 * q);
        }
#pragma unroll
        for (int j = 0; j < 2; j++) {
            pbh[j] = *(const uint4*)(Bph + (size_t)bk * bRow + (bu0 + j) * 8);
            pbl[j] = *(const uint4*)(Bpl + (size_t)bk * bRow + (bu0 + j) * 8);
        }
    }

    for (int k0 = 0; k0 < KT; k0 += 32) {
        __syncthreads();
#pragma unroll
        for (int q = 0; q < 4; q++) {
            const uint32_t off = (uint32_t)(tid * 64 + ((q ^ ((tid >> 1) & 3)) << 4));
            *(uint4*)(sm + OFF_AH + off) = pah[q];
            *(uint4*)(sm + OFF_AL + off) = pal[q];
        }
#pragma unroll
        for (int j = 0; j < 2; j++) {
            const int u = bu0 + j;
            const uint32_t off = (uint32_t)(bk * 256 + ((u ^ (bk & 7)) << 4));
            *(uint4*)(sm + OFF_BH + off) = pbh[j];
            *(uint4*)(sm + OFF_BL + off) = pbl[j];
        }
        __syncthreads();

        if (k0 + 32 < KT) {
            const __nv_bfloat16* ar = Ah + (size_t)(mBase + tid) * KT + k0 + 32;
            const __nv_bfloat16* al = Al + (size_t)(mBase + tid) * KT + k0 + 32;
#pragma unroll
            for (int q = 0; q < 4; q++) {
                pah[q] = *(const uint4*)(ar + 8 * q);
                pal[q] = *(const uint4*)(al + 8 * q);
            }
#pragma unroll
            for (int j = 0; j < 2; j++) {
                pbh[j] = *(const uint4*)(Bph + (size_t)(k0 + 32 + bk) * bRow + (bu0 + j) * 8);
                pbl[j] = *(const uint4*)(Bpl + (size_t)(k0 + 32 + bk) * bRow + (bu0 + j) * 8);
            }
        }

#pragma unroll
        for (int kk = 0; kk < 32; kk += 16) {
            uint32_t bf[8][2], af[4][4];
            const int krow = kk + (lane & 15);
            const int ncolHalf = (lane >> 4) * 8;
            const int arow = (lane & 15);
            const int acol = kk + (lane >> 4) * 8;

            // B hi
#pragma unroll
            for (int ni = 0; ni < 4; ni++) {
                const int nn = nw + ni * 16 + ncolHalf;
                uint32_t ad = sb + OFF_BH
                    + (uint32_t)(krow * 256 + ((((nn >> 3) ^ (krow & 7))) << 4));
                LDSM4T(bf[2 * ni][0], bf[2 * ni][1], bf[2 * ni + 1][0], bf[2 * ni + 1][1], ad);
            }
            // A hi
#pragma unroll
            for (int mi = 0; mi < 4; mi++) {
                const int r = mw + mi * 16 + arow;
                uint32_t ad = sb + OFF_AH
                    + (uint32_t)(r * 64 + ((((acol >> 3) ^ ((r >> 1) & 3))) << 4));
                LDSM4(af[mi][0], af[mi][1], af[mi][2], af[mi][3], ad);
            }
#pragma unroll
            for (int mi = 0; mi < 4; mi++)
#pragma unroll
                for (int g = 0; g < 8; g++) MMA(acc[mi][g], af[mi], bf[g]);
            // A lo
#pragma unroll
            for (int mi = 0; mi < 4; mi++) {
                const int r = mw + mi * 16 + arow;
                uint32_t ad = sb + OFF_AL
                    + (uint32_t)(r * 64 + ((((acol >> 3) ^ ((r >> 1) & 3))) << 4));
                LDSM4(af[mi][0], af[mi][1], af[mi][2], af[mi][3], ad);
            }
#pragma unroll
            for (int mi = 0; mi < 4; mi++)
#pragma unroll
                for (int g = 0; g < 8; g++) MMA(acc[mi][g], af[mi], bf[g]);
            // B lo
#pragma unroll
            for (int ni = 0; ni < 4; ni++) {
                const int nn = nw + ni * 16 + ncolHalf;
                uint32_t ad = sb + OFF_BL
                    + (uint32_t)(krow * 256 + ((((nn >> 3) ^ (krow & 7))) << 4));
                LDSM4T(bf[2 * ni][0], bf[2 * ni][1], bf[2 * ni + 1][0], bf[2 * ni + 1][1], ad);
            }
            // A hi again
#pragma unroll
            for (int mi = 0; mi < 4; mi++) {
                const int r = mw + mi * 16 + arow;
                uint32_t ad = sb + OFF_AH
                    + (uint32_t)(r * 64 + ((((acol >> 3) ^ ((r >> 1) & 3))) << 4));
                LDSM4(af[mi][0], af[mi][1], af[mi][2], af[mi][3], ad);
            }
#pragma unroll
            for (int mi = 0; mi < 4; mi++)
#pragma unroll
                for (int g = 0; g < 8; g++) MMA(acc[mi][g], af[mi], bf[g]);
        }
    }

    // ---- epilogue ----
#pragma unroll
    for (int mi = 0; mi < 4; mi++) {
        const int m_t = mBase + mw + mi * 16 + (lane >> 2);
        const int m_b = m_t + 8;
        const float inv_t = gg[m_t] * rsqrtf(vv[m_t] + EPSF);
        const float bt_t  = bb[m_t] - mm[m_t] * inv_t;
        const float inv_b = gg[m_b] * rsqrtf(vv[m_b] + EPSF);
        const float bt_b  = bb[m_b] - mm[m_b] * inv_b;
#pragma unroll
        for (int g = 0; g < 8; g++) {
            const int hw = hw0 + nw + g * 8 + 2 * (lane & 3);
            float vtx = fmaxf(fmaf(acc[mi][g][0], inv_t, bt_t), 0.f);
            float vty = fmaxf(fmaf(acc[mi][g][1], inv_t, bt_t), 0.f);
            float vbx = fmaxf(fmaf(acc[mi][g][2], inv_b, bt_b), 0.f);
            float vby = fmaxf(fmaf(acc[mi][g][3], inv_b, bt_b), 0.f);
            if (MODE == 1) {
                float* rowT = Cf + (size_t)nbat * cBatch + (size_t)m_t * cRow;
                float* rowB = Cf + (size_t)nbat * cBatch + (size_t)m_b * cRow;
                *(float2*)(rowT + hw) = make_float2(vtx, vty);
                *(float2*)(rowB + hw) = make_float2(vbx, vby);
            } else {
                __nv_bfloat162 hT = __float22bfloat162_rn(make_float2(vtx, vty));
                __nv_bfloat162 hB = __float22bfloat162_rn(make_float2(vbx, vby));
                float2 fT = __bfloat1622float2(hT);
                float2 fB = __bfloat1622float2(hB);
                __nv_bfloat162 lT = __float22bfloat162_rn(make_float2(vtx - fT.x, vty - fT.y));
                __nv_bfloat162 lB = __float22bfloat162_rn(make_float2(vbx - fB.x, vby - fB.y));
                size_t oT = (size_t)nbat * cBatch + (size_t)m_t * cRow + hw;
                size_t oB = (size_t)nbat * cBatch + (size_t)m_b * cRow + hw;
                *(__nv_bfloat162*)(Ch + oT) = hT;
                *(__nv_bfloat162*)(Ch + oB) = hB;
                *(__nv_bfloat162*)(Cl + oT) = lT;
                *(__nv_bfloat162*)(Cl + oB) = lB;
            }
        }
    }
}

// ---------------------------------------------------------------------------
// Attention: 128 threads, 2 pixels/thread; ctx written as hi/lo bf16 planes.
// ---------------------------------------------------------------------------
__global__ void __launch_bounds__(128) attn_kernel(
    const float* __restrict__ q,
    __nv_bfloat16* __restrict__ ch, __nv_bfloat16* __restrict__ cl)
{
    __shared__ float k_sh[KCC * KK];
    __shared__ float v_sh[KCC * KK];
    const int pixBase = blockIdx.x * 256;
    const int n = pixBase >> 14;
    for (int i = threadIdx.x; i < KCC * KK; i += 128) {
        k_sh[i] = g_kbuf[n * KCC * KK + i];
        v_sh[i] = g_vbuf[n * KCC * KK + i];
    }
    __syncthreads();

    const int c0 = pixBase + threadIdx.x;
    float sim[2][KK];
#pragma unroll
    for (int u = 0; u < 2; u++)
#pragma unroll
        for (int j = 0; j < KK; j++) sim[u][j] = 0.f;

    for (int c = 0; c < KCC; c++) {
        const float* qc = q + (size_t)c * TOT + c0;
        float q0 = qc[0], q1 = qc[128];
#pragma unroll
        for (int j = 0; j < KK; j++) {
            const float kc = k_sh[c * KK + j];
            sim[0][j] = fmaf(q0, kc, sim[0][j]);
            sim[1][j] = fmaf(q1, kc, sim[1][j]);
        }
    }

#pragma unroll
    for (int u = 0; u < 2; u++) {
        float mx = -1e30f;
#pragma unroll
        for (int j = 0; j < KK; j++) { sim[u][j] *= 0.0625f; mx = fmaxf(mx, sim[u][j]); }
        float s = 0.f;
#pragma unroll
        for (int j = 0; j < KK; j++) { sim[u][j] = __expf(sim[u][j] - mx); s += sim[u][j]; }
        const float rs = 1.f / s;
#pragma unroll
        for (int j = 0; j < KK; j++) sim[u][j] *= rs;
    }

    for (int c = 0; c < KCC; c++) {
        float a0 = 0.f, a1 = 0.f;
#pragma unroll
        for (int j = 0; j < KK; j++) {
            const float vc = v_sh[c * KK + j];
            a0 = fmaf(sim[0][j], vc, a0);
            a1 = fmaf(sim[1][j], vc, a1);
        }
        size_t o = (size_t)c * TOT + c0;
        __nv_bfloat16 h0 = __float2bfloat16(a0);
        __nv_bfloat16 h1 = __float2bfloat16(a1);
        ch[o]       = h0;
        ch[o + 128] = h1;
        cl[o]       = __float2bfloat16(a0 - __bfloat162float(h0));
        cl[o + 128] = __float2bfloat16(a1 - __bfloat162float(h1));
    }
}

// ---------------------------------------------------------------------------
// Launch
// ---------------------------------------------------------------------------
extern "C" void kernel_launch(void* const* d_in, const int* in_sizes, int n_in,
                              void* d_out, int out_size)
{
    const float* x     = (const float*)d_in[0];
    const float* proxy = (const float*)d_in[1];

    const float *w_p1, *w_p2, *w_o1, *w_o2, *w_d, *w_u;
    const float *p1g,*p1b,*p1m,*p1v, *p2g,*p2b,*p2m,*p2v;
    const float *o1g,*o1b,*o1m,*o1v, *o2g,*o2b,*o2m,*o2v;
    const float *dg,*db,*dm,*dv, *ug,*ub,*um,*uv;

    if (in_sizes[3] == KCC * KCC) {
        w_p1=(const float*)d_in[2]; w_p2=(const float*)d_in[3];
        w_o1=(const float*)d_in[4]; w_o2=(const float*)d_in[5];
        w_d =(const float*)d_in[6]; w_u =(const float*)d_in[7];
        p1g=(const float*)d_in[8];  p1b=(const float*)d_in[9];
        p1m=(const float*)d_in[10]; p1v=(const float*)d_in[11];
        p2g=(const float*)d_in[12]; p2b=(const float*)d_in[13];
        p2m=(const float*)d_in[14]; p2v=(const float*)d_in[15];
        o1g=(const float*)d_in[16]; o1b=(const float*)d_in[17];
        o1m=(const float*)d_in[18]; o1v=(const float*)d_in[19];
        o2g=(const float*)d_in[20]; o2b=(const float*)d_in[21];
        o2m=(const float*)d_in[22]; o2v=(const float*)d_in[23];
        dg =(const float*)d_in[24]; db =(const float*)d_in[25];
        dm =(const float*)d_in[26]; dv =(const float*)d_in[27];
        ug =(const float*)d_in[28]; ub =(const float*)d_in[29];
        um =(const float*)d_in[30]; uv =(const float*)d_in[31];
    } else {
        w_p1=(const float*)d_in[2];
        p1g=(const float*)d_in[3];  p1b=(const float*)d_in[4];
        p1m=(const float*)d_in[5];  p1v=(const float*)d_in[6];
        w_p2=(const float*)d_in[7];
        p2g=(const float*)d_in[8];  p2b=(const float*)d_in[9];
        p2m=(const float*)d_in[10]; p2v=(const float*)d_in[11];
        w_o1=(const float*)d_in[12];
        o1g=(const float*)d_in[13]; o1b=(const float*)d_in[14];
        o1m=(const float*)d_in[15]; o1v=(const float*)d_in[16];
        w_o2=(const float*)d_in[17];
        o2g=(const float*)d_in[18]; o2b=(const float*)d_in[19];
        o2m=(const float*)d_in[20]; o2v=(const float*)d_in[21];
        w_d =(const float*)d_in[22];
        dg =(const float*)d_in[23]; db =(const float*)d_in[24];
        dm =(const float*)d_in[25]; dv =(const float*)d_in[26];
        w_u =(const float*)d_in[27];
        ug =(const float*)d_in[28]; ub =(const float*)d_in[29];
        um =(const float*)d_in[30]; uv =(const float*)d_in[31];
    }

    float* out = (float*)d_out;

    __nv_bfloat16 *xh,*xl,*t1h,*t1l,*chp,*clp,*w1h,*w1l,*w2h,*w2l,*wuh,*wul;
    float* qb;
    cudaGetSymbolAddress((void**)&xh,  g_xh);
    cudaGetSymbolAddress((void**)&xl,  g_xl);
    cudaGetSymbolAddress((void**)&t1h, g_t1h);
    cudaGetSymbolAddress((void**)&t1l, g_t1l);
    cudaGetSymbolAddress((void**)&qb,  g_q);
    cudaGetSymbolAddress((void**)&chp, g_ch);
    cudaGetSymbolAddress((void**)&clp, g_cl);
    cudaGetSymbolAddress((void**)&w1h, g_w1h);
    cudaGetSymbolAddress((void**)&w1l, g_w1l);
    cudaGetSymbolAddress((void**)&w2h, g_w2h);
    cudaGetSymbolAddress((void**)&w2l, g_w2l);
    cudaGetSymbolAddress((void**)&wuh, g_wuh);
    cudaGetSymbolAddress((void**)&wul, g_wul);

    // 0) pre-split weights and x
    split_kernel<<<(KCC * CIN / 4 + 255) / 256, 256>>>(w_p1, w1h, w1l, KCC * CIN / 4);
    split_kernel<<<(KCC * KCC / 4 + 255) / 256, 256>>>(w_p2, w2h, w2l, KCC * KCC / 4);
    split_kernel<<<(CIN * KCC / 4 + 255) / 256, 256>>>(w_u,  wuh, wul, CIN * KCC / 4);
    {
        size_t n4 = (size_t)CIN * TOT / 4;
        split_kernel<<<(unsigned)((n4 + 255) / 256), 256>>>(x, xh, xl, n4);
    }

    // 1) proxy -> k, v
    proxy_kernel<<<NB, KCC>>>(proxy,
        w_o1, o1g, o1b, o1m, o1v,
        w_o2, o2g, o2b, o2m, o2v,
        w_d,  dg,  db,  dm,  dv);

    // 2) t1 = bn_relu(w_p1 @ x)  -> hi/lo planes [256][TOT]
    gemm_mma<0><<<dim3(TOT / 128, 1), 256>>>(
        w1h, w1l, CIN,
        xh, xl, HW, (long)CIN * HW,
        nullptr, t1h, t1l, TOT, HW,
        p1g, p1b, p1m, p1v);

    // 3) q = bn_relu(w_p2 @ t1)  -> fp32 [256][TOT]
    gemm_mma<1><<<dim3(TOT / 128, 1), 256>>>(
        w2h, w2l, KCC,
        t1h, t1l, TOT, HW,
        qb, nullptr, nullptr, TOT, HW,
        p2g, p2b, p2m, p2v);

    // 4) attention q -> ctx hi/lo planes
    attn_kernel<<<TOT / 256, 128>>>(qb, chp, clp);

    // 5) out = bn_relu(w_u @ ctx) -> fp32 NCHW
    gemm_mma<1><<<dim3(TOT / 128, CIN / 256), 256>>>(
        wuh, wul, KCC,
        chp, clp, TOT, HW,
        out, nullptr, nullptr, HW, (long)CIN * HW,
        ug, ub, um, uv);
}